// round 14
// baseline (speedup 1.0000x reference)
#include <cuda_runtime.h>
#include <cuda_bf16.h>
#include <math.h>
#include <stdint.h>

#define Bb   32
#define Ss   2048
#define Hh   256
#define G4   1024
#define Ll   2
#define CL   4
#define NCTA (Bb * CL)

// ---------------- device scratch ----------------
__device__ float g_xp[(size_t)Bb * Ss * G4];                 // 256 MB
__device__ float g_y0[(size_t)Bb * Ss * Hh];                 // 64 MB
__device__ __nv_bfloat16 g_ah[(size_t)Bb * Ss * Hh];         // X hi (bf16)
__device__ __nv_bfloat16 g_al[(size_t)Bb * Ss * Hh];         // X lo
__device__ __nv_bfloat16 g_bh[(size_t)G4 * Hh];              // W hi
__device__ __nv_bfloat16 g_bl[(size_t)G4 * Hh];              // W lo

// ---------------- helpers ----------------
typedef unsigned long long ull;
__device__ __forceinline__ void unpack2(ull v, float& lo, float& hi) {
    asm("mov.b64 {%0,%1},%2;" : "=f"(lo), "=f"(hi) : "l"(v));
}
__device__ __forceinline__ void fma2(ull& acc, ull a, ull b) {
    asm("fma.rn.f32x2 %0,%1,%2,%0;" : "+l"(acc) : "l"(a), "l"(b));
}
__device__ __forceinline__ unsigned pack_bf16x2(float lo, float hi) {
    unsigned d;
    asm("cvt.rn.bf16x2.f32 %0, %1, %2;" : "=r"(d) : "f"(hi), "f"(lo));
    return d;
}
__device__ __forceinline__ ull expand_a(unsigned w) {
    unsigned lo, hi;
    asm("shl.b32 %0, %1, 16;" : "=r"(lo) : "r"(w));
    asm("and.b32 %0, %1, 0xFFFF0000;" : "=r"(hi) : "r"(w));
    ull r; asm("mov.b64 %0,{%1,%2};" : "=l"(r) : "r"(lo), "r"(hi));
    return r;
}
__device__ __forceinline__ ull expand_b(unsigned w) {
    unsigned lo, hi;
    asm("mul.lo.s32 %0, %1, 65536;" : "=r"(lo) : "r"(w));
    asm("and.b32 %0, %1, 0xFFFF0000;" : "=r"(hi) : "r"(w));
    ull r; asm("mov.b64 %0,{%1,%2};" : "=l"(r) : "r"(lo), "r"(hi));
    return r;
}
__device__ __forceinline__ float tanh_f(float x) {
    float y; asm("tanh.approx.f32 %0,%1;" : "=f"(y) : "f"(x)); return y;
}
__device__ __forceinline__ float sig_f(float x) {
    return fmaf(0.5f, tanh_f(0.5f * x), 0.5f);
}
__device__ __forceinline__ uint32_t smem_u32(const void* p) {
    uint32_t a;
    asm("{ .reg .u64 t; cvta.to.shared.u64 t, %1; cvt.u32.u64 %0, t; }" : "=r"(a) : "l"(p));
    return a;
}
__device__ __forceinline__ uint32_t mapa_u32(uint32_t saddr, int rank) {
    uint32_t rem;
    asm("mapa.shared::cluster.u32 %0, %1, %2;" : "=r"(rem) : "r"(saddr), "r"(rank));
    return rem;
}
#define CLUSTER_ARRIVE() asm volatile("barrier.cluster.arrive.aligned;" ::: "memory")
#define CLUSTER_WAIT()   asm volatile("barrier.cluster.wait.aligned;" ::: "memory")

__device__ __forceinline__ void mbar_init(uint32_t a, uint32_t cnt) {
    asm volatile("mbarrier.init.shared.b64 [%0], %1;" :: "r"(a), "r"(cnt) : "memory");
}
__device__ __forceinline__ void mbar_arrive_local(uint32_t a) {
    asm volatile("mbarrier.arrive.shared.b64 _, [%0];" :: "r"(a) : "memory");
}
__device__ __forceinline__ void mbar_arm_tx(uint32_t a, uint32_t tx) {
    asm volatile("mbarrier.arrive.expect_tx.shared.b64 _, [%0], %1;"
                 :: "r"(a), "r"(tx) : "memory");
}
__device__ __forceinline__ void mbar_wait_cluster(uint32_t a, uint32_t parity) {
    asm volatile(
        "{\n\t.reg .pred P;\n"
        "LW%=:\n\t"
        "mbarrier.try_wait.parity.acquire.cluster.shared::cta.b64 P, [%0], %1, 0x989680;\n\t"
        "@P bra LD%=;\n\t"
        "bra LW%=;\n"
        "LD%=:\n\t}"
        :: "r"(a), "r"(parity) : "memory");
}
// remote store delivering complete_tx (4 bytes) to the destination CTA's mbarrier
__device__ __forceinline__ void st_async_f32(uint32_t raddr, uint32_t rmbar, float v) {
    asm volatile(
        "st.async.weak.shared::cluster.mbarrier::complete_tx::bytes.b32 [%0], %1, [%2];"
        :: "r"(raddr), "r"(__float_as_uint(v)), "r"(rmbar) : "memory");
}

__device__ __forceinline__ void ldsm4(uint32_t& r0, uint32_t& r1, uint32_t& r2, uint32_t& r3,
                                      uint32_t addr) {
    asm volatile("ldmatrix.sync.aligned.m8n8.x4.shared.b16 {%0,%1,%2,%3}, [%4];"
                 : "=r"(r0), "=r"(r1), "=r"(r2), "=r"(r3) : "r"(addr));
}
__device__ __forceinline__ void mma16816(float* c, uint32_t a0, uint32_t a1, uint32_t a2,
                                         uint32_t a3, uint32_t b0, uint32_t b1) {
    asm volatile(
        "mma.sync.aligned.m16n8k16.row.col.f32.bf16.bf16.f32 "
        "{%0,%1,%2,%3}, {%4,%5,%6,%7}, {%8,%9}, {%0,%1,%2,%3};"
        : "+f"(c[0]), "+f"(c[1]), "+f"(c[2]), "+f"(c[3])
        : "r"(a0), "r"(a1), "r"(a2), "r"(a3), "r"(b0), "r"(b1));
}
__device__ __forceinline__ void cpa16(uint32_t dst, const void* src) {
    asm volatile("cp.async.cg.shared.global [%0], [%1], 16;" :: "r"(dst), "l"(src) : "memory");
}
#define CPA_COMMIT() asm volatile("cp.async.commit_group;" ::: "memory")
#define CPA_WAIT(N)  asm volatile("cp.async.wait_group %0;" :: "n"(N) : "memory")

// ---------------- split kernel: f32 -> bf16 hi + bf16 lo ----------------
__global__ __launch_bounds__(256) void conv_split(const float* __restrict__ src,
                                                  __nv_bfloat16* __restrict__ hi,
                                                  __nv_bfloat16* __restrict__ lo,
                                                  int n4)
{
    int i = blockIdx.x * blockDim.x + threadIdx.x;
    if (i >= n4) return;
    float4 v = ((const float4*)src)[i];
    __nv_bfloat16 h0 = __float2bfloat16(v.x);
    __nv_bfloat16 h1 = __float2bfloat16(v.y);
    __nv_bfloat16 h2 = __float2bfloat16(v.z);
    __nv_bfloat16 h3 = __float2bfloat16(v.w);
    __nv_bfloat16 l0 = __float2bfloat16(v.x - __bfloat162float(h0));
    __nv_bfloat16 l1 = __float2bfloat16(v.y - __bfloat162float(h1));
    __nv_bfloat16 l2 = __float2bfloat16(v.z - __bfloat162float(h2));
    __nv_bfloat16 l3 = __float2bfloat16(v.w - __bfloat162float(h3));
    ((__nv_bfloat162*)hi)[2 * i + 0] = __nv_bfloat162(h0, h1);
    ((__nv_bfloat162*)hi)[2 * i + 1] = __nv_bfloat162(h2, h3);
    ((__nv_bfloat162*)lo)[2 * i + 0] = __nv_bfloat162(l0, l1);
    ((__nv_bfloat162*)lo)[2 * i + 1] = __nv_bfloat162(l2, l3);
}

// ---------------- warp-MMA GEMM with cp.async double buffering (unchanged) ----------------
#define KSTR 72   // halves per smem row (144 B) -> conflict-free ldmatrix

static constexpr int STG_BYTES = 128 * KSTR * 2;
static constexpr int SMB_BIAS  = 8 * STG_BYTES;
static constexpr int SMB_TOT   = SMB_BIAS + 128 * 4;
__device__ __forceinline__ uint32_t stg_off(int arr, int st) {
    return (uint32_t)((arr * 2 + st) * STG_BYTES);
}

__global__ __launch_bounds__(256, 1) void gemm_bf16mma(const float* __restrict__ b1g,
                                                       const float* __restrict__ b2g,
                                                       int layer)
{
    extern __shared__ char smem[];
    const uint32_t sb = smem_u32(smem);
    const int tid = threadIdx.x;
    const int lane = tid & 31;
    const int w = tid >> 5;
    const int wm = (w & 3) * 32;
    const int wn = (w >> 2) * 64;
    const int m0 = blockIdx.y * 128;
    const int n0 = blockIdx.x * 128;

    if (tid < 128) {
        ((float*)(smem + SMB_BIAS))[tid] =
            b1g[layer * G4 + n0 + tid] + b2g[layer * G4 + n0 + tid];
    }

    const uint4* Ah = (const uint4*)g_ah;
    const uint4* Al = (const uint4*)g_al;
    const uint4* Bh = (const uint4*)g_bh;
    const uint4* Bl = (const uint4*)g_bl;

    float acc[2][8][4];
#pragma unroll
    for (int i = 0; i < 2; i++)
#pragma unroll
        for (int j = 0; j < 8; j++)
#pragma unroll
            for (int k = 0; k < 4; k++) acc[i][j][k] = 0.0f;

    const int a_row = (lane & 15);
    const int a_kof = (lane >> 4) << 3;
    const int b_row = (lane & 7) + ((lane >> 4) << 3);
    const int b_kof = ((lane >> 3) & 1) << 3;

    auto load_stage = [&](int kc, int st) {
#pragma unroll
        for (int r = 0; r < 4; r++) {
            int i = tid + r * 256;
            int row = i >> 3, c8 = i & 7;
            uint32_t d = (uint32_t)(row * (KSTR * 2) + c8 * 16);
            int gaix = (m0 + row) * 32 + kc * 8 + c8;
            int gbix = (n0 + row) * 32 + kc * 8 + c8;
            cpa16(sb + stg_off(0, st) + d, &Ah[gaix]);
            cpa16(sb + stg_off(1, st) + d, &Al[gaix]);
            cpa16(sb + stg_off(2, st) + d, &Bh[gbix]);
            cpa16(sb + stg_off(3, st) + d, &Bl[gbix]);
        }
        CPA_COMMIT();
    };

    load_stage(0, 0);

    for (int kc = 0; kc < 4; kc++) {
        const int st = kc & 1;
        if (kc < 3) { load_stage(kc + 1, st ^ 1); CPA_WAIT(1); }
        else        { CPA_WAIT(0); }
        __syncthreads();

        const uint32_t bAH = sb + stg_off(0, st);
        const uint32_t bAL = sb + stg_off(1, st);
        const uint32_t bBH = sb + stg_off(2, st);
        const uint32_t bBL = sb + stg_off(3, st);

#pragma unroll
        for (int ks = 0; ks < 4; ks++) {
            const int kh = ks * 16;
            uint32_t ah[2][4], al[2][4];
#pragma unroll
            for (int mt = 0; mt < 2; mt++) {
                uint32_t off = (uint32_t)(((wm + mt * 16 + a_row) * KSTR + kh + a_kof) * 2);
                ldsm4(ah[mt][0], ah[mt][1], ah[mt][2], ah[mt][3], bAH + off);
                ldsm4(al[mt][0], al[mt][1], al[mt][2], al[mt][3], bAL + off);
            }
            uint32_t bh[4][4], bl[4][4];
#pragma unroll
            for (int p = 0; p < 4; p++) {
                uint32_t off = (uint32_t)(((wn + p * 16 + b_row) * KSTR + kh + b_kof) * 2);
                ldsm4(bh[p][0], bh[p][1], bh[p][2], bh[p][3], bBH + off);
                ldsm4(bl[p][0], bl[p][1], bl[p][2], bl[p][3], bBL + off);
            }
#pragma unroll
            for (int mt = 0; mt < 2; mt++) {
#pragma unroll
                for (int p = 0; p < 4; p++) {
                    mma16816(acc[mt][2 * p + 0], ah[mt][0], ah[mt][1], ah[mt][2], ah[mt][3],
                             bh[p][0], bh[p][1]);
                    mma16816(acc[mt][2 * p + 0], ah[mt][0], ah[mt][1], ah[mt][2], ah[mt][3],
                             bl[p][0], bl[p][1]);
                    mma16816(acc[mt][2 * p + 0], al[mt][0], al[mt][1], al[mt][2], al[mt][3],
                             bh[p][0], bh[p][1]);
                    mma16816(acc[mt][2 * p + 1], ah[mt][0], ah[mt][1], ah[mt][2], ah[mt][3],
                             bh[p][2], bh[p][3]);
                    mma16816(acc[mt][2 * p + 1], ah[mt][0], ah[mt][1], ah[mt][2], ah[mt][3],
                             bl[p][2], bl[p][3]);
                    mma16816(acc[mt][2 * p + 1], al[mt][0], al[mt][1], al[mt][2], al[mt][3],
                             bh[p][2], bh[p][3]);
                }
            }
        }
        __syncthreads();
    }

    const float* bias = (const float*)(smem + SMB_BIAS);
    const int gid = lane >> 2;
    const int tig = lane & 3;
#pragma unroll
    for (int mt = 0; mt < 2; mt++) {
#pragma unroll
        for (int nt = 0; nt < 8; nt++) {
            int col = wn + nt * 8 + tig * 2;
            float b0 = bias[col], b1 = bias[col + 1];
            int gm0 = m0 + wm + mt * 16 + gid;
            float* p0 = &g_xp[(size_t)gm0 * G4 + n0 + col];
            float* p1 = &g_xp[(size_t)(gm0 + 8) * G4 + n0 + col];
            float2 v0 = { acc[mt][nt][0] + b0, acc[mt][nt][1] + b1 };
            float2 v1 = { acc[mt][nt][2] + b0, acc[mt][nt][3] + b1 };
            *(float2*)p0 = v0;
            *(float2*)p1 = v1;
        }
    }
}

// ---------------- clustered LSTM recurrence: R11 + rotated chunks ----------------
// R11 base (per-source mbarriers, redp double-buffer, single __syncthreads/step,
// bf16 wregs). Change vs R11: chunk rotation — half0 consumes chunks
// {rank, rank+1}, half1 {rank+2, rank+3} (mod 4), so the dot starts on the
// self-pushed chunk (near-zero DSMEM transit) and remote chunks are consumed
// 150+ cycles into the dot, hiding their transit. mbar arming on warp 14.
__global__ __launch_bounds__(512, 1) __cluster_dims__(CL, 1, 1)
void lstm_rec(const float* __restrict__ Whh,
              float* __restrict__ yout,
              float* __restrict__ hT,
              float* __restrict__ cT,
              int layer)
{
    __shared__ __align__(16) float h_s[2][Hh];        // +1024 B between buffers
    __shared__ float redp[2][2][4][64];               // [t&1][half][gate][nl]
    __shared__ __align__(8) unsigned long long mbars[2][CL];

    const int tid = threadIdx.x;
    uint32_t rank;
    asm("mov.u32 %0, %%cluster_ctarank;" : "=r"(rank));
    const int b  = blockIdx.x / CL;
    const int n0 = (int)rank * 64;

    const int half = tid >> 8;            // 0/1
    const int sub  = tid & 255;
    const int gate = sub >> 6;
    const int nl   = sub & 63;
    const int G    = gate * 256 + n0 + nl;

    // rotated chunks: half0 -> {rank, rank+1}, half1 -> {rank+2, rank+3}
    const int cA = ((int)rank + 2 * half) & 3;
    const int cB = (cA + 1) & 3;

    const float* Wbase = Whh + (size_t)layer * G4 * Hh + (size_t)G * Hh;
    const float4* WrowA = (const float4*)(Wbase + cA * 64);
    const float4* WrowB = (const float4*)(Wbase + cB * 64);
    unsigned wregA[32], wregB[32];
#pragma unroll
    for (int q = 0; q < 16; q++) {
        float4 va = __ldg(&WrowA[q]);
        wregA[2 * q + 0] = pack_bf16x2(va.x, va.y);
        wregA[2 * q + 1] = pack_bf16x2(va.z, va.w);
        float4 vb = __ldg(&WrowB[q]);
        wregB[2 * q + 0] = pack_bf16x2(vb.x, vb.y);
        wregB[2 * q + 1] = pack_bf16x2(vb.z, vb.w);
    }

    const uint32_t lh0 = smem_u32(&h_s[0][0]);
    const uint32_t lm0 = smem_u32(&mbars[0][0]);

    for (int i = tid; i < Hh; i += 512) h_s[0][i] = 0.0f;
    if (tid == 0) {
#pragma unroll
        for (int i = 0; i < 2 * CL; i++) mbar_init(lm0 + i * 8u, 1);
#pragma unroll
        for (int p = 0; p < CL; p++) mbar_arrive_local(lm0 + p * 8u);  // buffer 0 phase 0 done
    }
    __syncthreads();
    CLUSTER_ARRIVE();
    CLUSTER_WAIT();

    const float* xp = g_xp + (size_t)b * Ss * G4 + G;
    float* y = layer ? yout : g_y0;
    float* ybase = y + (size_t)b * Ss * Hh;

    float c_reg = 0.0f;

    // hoisted remote bases for cell threads (buffer offsets added per step)
    const int n_cell = n0 + (tid & 63);
    uint32_t rhB[CL], rmB[CL];
#pragma unroll
    for (int p = 0; p < CL; p++) {
        rhB[p] = mapa_u32(lh0 + (uint32_t)n_cell * 4u, p);
        rmB[p] = mapa_u32(lm0, p);
    }
    const uint32_t my_mofs = rank * 8u;   // mbars[.][my_rank]

    float xpv = (half == 0) ? __ldg(&xp[0]) : 0.0f;

    for (int t = 0; t < Ss; t++) {
        const uint32_t cb = (uint32_t)(t & 1);
        const uint32_t nb = cb ^ 1u;
        const uint32_t par = (uint32_t)((t >> 1) & 1);

        // arm next buffer's 4 source-mbars (warp 14, off the cell path)
        if ((tid & ~3) == 448) mbar_arm_tx(lm0 + (nb * CL + (uint32_t)(tid & 3)) * 8u, 256u);

        float xpn = (half == 0)
                  ? __ldg(&xp[(size_t)(t + 1 < Ss ? t + 1 : t) * G4]) : 0.0f;

        // ---- dot: chunk cA first (self for half0), then cB ----
        const ulonglong2* hvA = (const ulonglong2*)&h_s[cb][cA * 64];
        const ulonglong2* hvB = (const ulonglong2*)&h_s[cb][cB * 64];
        ull acc0 = 0ull, acc1 = 0ull;

        mbar_wait_cluster(lm0 + (cb * CL + (uint32_t)cA) * 8u, par);
#pragma unroll
        for (int q = 0; q < 16; q++) {
            ulonglong2 hh = hvA[q];
            fma2(acc0, hh.x, expand_a(wregA[2 * q + 0]));
            fma2(acc1, hh.y, expand_b(wregA[2 * q + 1]));
        }
        mbar_wait_cluster(lm0 + (cb * CL + (uint32_t)cB) * 8u, par);
#pragma unroll
        for (int q = 0; q < 16; q++) {
            ulonglong2 hh = hvB[q];
            fma2(acc0, hh.x, expand_a(wregB[2 * q + 0]));
            fma2(acc1, hh.y, expand_b(wregB[2 * q + 1]));
        }

        float s0, s1, s2, s3;
        unpack2(acc0, s0, s1);
        unpack2(acc1, s2, s3);
        redp[cb][half][gate][nl] = ((s0 + s2) + (s1 + s3)) + xpv;
        __syncthreads();

        if (tid < 64) {
            float iv = redp[cb][0][0][tid] + redp[cb][1][0][tid];
            float fv = redp[cb][0][1][tid] + redp[cb][1][1][tid];
            float gv = redp[cb][0][2][tid] + redp[cb][1][2][tid];
            float ov = redp[cb][0][3][tid] + redp[cb][1][3][tid];
            float c  = sig_f(fv) * c_reg + sig_f(iv) * tanh_f(gv);
            float h  = sig_f(ov) * tanh_f(c);
            c_reg = c;
            const uint32_t hofs = nb * (uint32_t)(Hh * 4);
            const uint32_t mofs = nb * (uint32_t)(CL * 8) + my_mofs;
            // self first (feeds own next-step chunk cA immediately), then peers
#pragma unroll
            for (int i = 0; i < CL; i++) {
                int p = ((int)rank + i) & (CL - 1);
                st_async_f32(rhB[p] + hofs, rmB[p] + mofs, h);
            }
            ybase[(size_t)t * Hh + n_cell] = h;
            if (t == Ss - 1) { hT[b * Hh + n_cell] = h; cT[b * Hh + n_cell] = c; }
        }
        xpv = xpn;
        // no second barrier: redp double-buffering makes next step's writes safe
    }

    // no CTA may exit while peers' st.async into its SMEM could be in flight
    CLUSTER_ARRIVE();
    CLUSTER_WAIT();
}

// ---------------- launch ----------------
extern "C" void kernel_launch(void* const* d_in, const int* in_sizes, int n_in,
                              void* d_out, int out_size)
{
    (void)in_sizes; (void)n_in; (void)out_size;
    const float* x    = (const float*)d_in[0];   // [B,S,H]
    const float* Wih  = (const float*)d_in[1];   // [L,4H,H]
    const float* bih  = (const float*)d_in[2];   // [L,4H]
    const float* Whh  = (const float*)d_in[3];   // [L,4H,H]
    const float* bhh  = (const float*)d_in[4];   // [L,4H]

    float* out = (float*)d_out;
    float* y_x = out;
    float* hT  = out + (size_t)Bb * Ss * Hh;
    float* cT  = hT + (size_t)Ll * Bb * Hh;

    cudaFuncSetAttribute(gemm_bf16mma, cudaFuncAttributeMaxDynamicSharedMemorySize, SMB_TOT);

    __nv_bfloat16 *ah, *al, *bh, *bl;
    cudaGetSymbolAddress((void**)&ah, g_ah);
    cudaGetSymbolAddress((void**)&al, g_al);
    cudaGetSymbolAddress((void**)&bh, g_bh);
    cudaGetSymbolAddress((void**)&bl, g_bl);
    float* y0;
    cudaGetSymbolAddress((void**)&y0, g_y0);

    const int nX4 = (Bb * Ss * Hh) / 4;
    const int nW4 = (G4 * Hh) / 4;

    dim3 ggrid(G4 / 128, (Bb * Ss) / 128);

    for (int layer = 0; layer < Ll; layer++) {
        const float* xin = layer ? (const float*)y0 : x;
        conv_split<<<nX4 / 256, 256>>>(xin, ah, al, nX4);
        conv_split<<<nW4 / 256, 256>>>(Wih + (size_t)layer * G4 * Hh, bh, bl, nW4);
        gemm_bf16mma<<<ggrid, 256, SMB_TOT>>>(bih, bhh, layer);
        lstm_rec<<<NCTA, 512>>>(Whh, y_x,
                                hT + (size_t)layer * Bb * Hh,
                                cT + (size_t)layer * Bb * Hh,
                                layer);
    }
}

// round 15
// speedup vs baseline: 1.0558x; 1.0558x over previous
#include <cuda_runtime.h>
#include <cuda_bf16.h>
#include <math.h>
#include <stdint.h>

#define Bb   32
#define Ss   2048
#define Hh   256
#define G4   1024
#define Ll   2
#define CL   4
#define NCTA (Bb * CL)

// ---------------- device scratch ----------------
__device__ float g_xp[(size_t)Bb * Ss * G4];                 // 256 MB
__device__ __nv_bfloat16 g_ah[(size_t)Bb * Ss * Hh];         // X hi (bf16); layer1: y0 hi
__device__ __nv_bfloat16 g_al[(size_t)Bb * Ss * Hh];         // X lo;        layer1: y0 lo
__device__ __nv_bfloat16 g_bh[(size_t)Ll * G4 * Hh];         // W hi (both layers)
__device__ __nv_bfloat16 g_bl[(size_t)Ll * G4 * Hh];         // W lo (both layers)

// ---------------- helpers ----------------
typedef unsigned long long ull;
__device__ __forceinline__ void unpack2(ull v, float& lo, float& hi) {
    asm("mov.b64 {%0,%1},%2;" : "=f"(lo), "=f"(hi) : "l"(v));
}
__device__ __forceinline__ void fma2(ull& acc, ull a, ull b) {
    asm("fma.rn.f32x2 %0,%1,%2,%0;" : "+l"(acc) : "l"(a), "l"(b));
}
__device__ __forceinline__ unsigned pack_bf16x2(float lo, float hi) {
    unsigned d;
    asm("cvt.rn.bf16x2.f32 %0, %1, %2;" : "=r"(d) : "f"(hi), "f"(lo));
    return d;
}
__device__ __forceinline__ ull expand_a(unsigned w) {
    unsigned lo, hi;
    asm("shl.b32 %0, %1, 16;" : "=r"(lo) : "r"(w));
    asm("and.b32 %0, %1, 0xFFFF0000;" : "=r"(hi) : "r"(w));
    ull r; asm("mov.b64 %0,{%1,%2};" : "=l"(r) : "r"(lo), "r"(hi));
    return r;
}
__device__ __forceinline__ ull expand_b(unsigned w) {
    unsigned lo, hi;
    asm("mul.lo.s32 %0, %1, 65536;" : "=r"(lo) : "r"(w));
    asm("and.b32 %0, %1, 0xFFFF0000;" : "=r"(hi) : "r"(w));
    ull r; asm("mov.b64 %0,{%1,%2};" : "=l"(r) : "r"(lo), "r"(hi));
    return r;
}
__device__ __forceinline__ float tanh_f(float x) {
    float y; asm("tanh.approx.f32 %0,%1;" : "=f"(y) : "f"(x)); return y;
}
__device__ __forceinline__ float sig_f(float x) {
    return fmaf(0.5f, tanh_f(0.5f * x), 0.5f);
}
__device__ __forceinline__ uint32_t smem_u32(const void* p) {
    uint32_t a;
    asm("{ .reg .u64 t; cvta.to.shared.u64 t, %1; cvt.u32.u64 %0, t; }" : "=r"(a) : "l"(p));
    return a;
}
__device__ __forceinline__ uint32_t mapa_u32(uint32_t saddr, int rank) {
    uint32_t rem;
    asm("mapa.shared::cluster.u32 %0, %1, %2;" : "=r"(rem) : "r"(saddr), "r"(rank));
    return rem;
}
#define CLUSTER_ARRIVE() asm volatile("barrier.cluster.arrive.aligned;" ::: "memory")
#define CLUSTER_WAIT()   asm volatile("barrier.cluster.wait.aligned;" ::: "memory")

__device__ __forceinline__ void mbar_init(uint32_t a, uint32_t cnt) {
    asm volatile("mbarrier.init.shared.b64 [%0], %1;" :: "r"(a), "r"(cnt) : "memory");
}
__device__ __forceinline__ void mbar_arrive_local(uint32_t a) {
    asm volatile("mbarrier.arrive.shared.b64 _, [%0];" :: "r"(a) : "memory");
}
__device__ __forceinline__ void mbar_arm_tx(uint32_t a, uint32_t tx) {
    asm volatile("mbarrier.arrive.expect_tx.shared.b64 _, [%0], %1;"
                 :: "r"(a), "r"(tx) : "memory");
}
__device__ __forceinline__ void mbar_wait_cluster(uint32_t a, uint32_t parity) {
    asm volatile(
        "{\n\t.reg .pred P;\n"
        "LW%=:\n\t"
        "mbarrier.try_wait.parity.acquire.cluster.shared::cta.b64 P, [%0], %1, 0x989680;\n\t"
        "@P bra LD%=;\n\t"
        "bra LW%=;\n"
        "LD%=:\n\t}"
        :: "r"(a), "r"(parity) : "memory");
}
// remote store delivering complete_tx (4 bytes) to the destination CTA's mbarrier
__device__ __forceinline__ void st_async_f32(uint32_t raddr, uint32_t rmbar, float v) {
    asm volatile(
        "st.async.weak.shared::cluster.mbarrier::complete_tx::bytes.b32 [%0], %1, [%2];"
        :: "r"(raddr), "r"(__float_as_uint(v)), "r"(rmbar) : "memory");
}

__device__ __forceinline__ void ldsm4(uint32_t& r0, uint32_t& r1, uint32_t& r2, uint32_t& r3,
                                      uint32_t addr) {
    asm volatile("ldmatrix.sync.aligned.m8n8.x4.shared.b16 {%0,%1,%2,%3}, [%4];"
                 : "=r"(r0), "=r"(r1), "=r"(r2), "=r"(r3) : "r"(addr));
}
__device__ __forceinline__ void mma16816(float* c, uint32_t a0, uint32_t a1, uint32_t a2,
                                         uint32_t a3, uint32_t b0, uint32_t b1) {
    asm volatile(
        "mma.sync.aligned.m16n8k16.row.col.f32.bf16.bf16.f32 "
        "{%0,%1,%2,%3}, {%4,%5,%6,%7}, {%8,%9}, {%0,%1,%2,%3};"
        : "+f"(c[0]), "+f"(c[1]), "+f"(c[2]), "+f"(c[3])
        : "r"(a0), "r"(a1), "r"(a2), "r"(a3), "r"(b0), "r"(b1));
}
__device__ __forceinline__ void cpa16(uint32_t dst, const void* src) {
    asm volatile("cp.async.cg.shared.global [%0], [%1], 16;" :: "r"(dst), "l"(src) : "memory");
}
#define CPA_COMMIT() asm volatile("cp.async.commit_group;" ::: "memory")
#define CPA_WAIT(N)  asm volatile("cp.async.wait_group %0;" :: "n"(N) : "memory")

// ---------------- split kernel: f32 -> bf16 hi + bf16 lo ----------------
__global__ __launch_bounds__(256) void conv_split(const float* __restrict__ src,
                                                  __nv_bfloat16* __restrict__ hi,
                                                  __nv_bfloat16* __restrict__ lo,
                                                  int n4)
{
    int i = blockIdx.x * blockDim.x + threadIdx.x;
    if (i >= n4) return;
    float4 v = ((const float4*)src)[i];
    __nv_bfloat16 h0 = __float2bfloat16(v.x);
    __nv_bfloat16 h1 = __float2bfloat16(v.y);
    __nv_bfloat16 h2 = __float2bfloat16(v.z);
    __nv_bfloat16 h3 = __float2bfloat16(v.w);
    __nv_bfloat16 l0 = __float2bfloat16(v.x - __bfloat162float(h0));
    __nv_bfloat16 l1 = __float2bfloat16(v.y - __bfloat162float(h1));
    __nv_bfloat16 l2 = __float2bfloat16(v.z - __bfloat162float(h2));
    __nv_bfloat16 l3 = __float2bfloat16(v.w - __bfloat162float(h3));
    ((__nv_bfloat162*)hi)[2 * i + 0] = __nv_bfloat162(h0, h1);
    ((__nv_bfloat162*)hi)[2 * i + 1] = __nv_bfloat162(h2, h3);
    ((__nv_bfloat162*)lo)[2 * i + 0] = __nv_bfloat162(l0, l1);
    ((__nv_bfloat162*)lo)[2 * i + 1] = __nv_bfloat162(l2, l3);
}

// ---------------- warp-MMA GEMM with cp.async double buffering ----------------
#define KSTR 72   // halves per smem row (144 B) -> conflict-free ldmatrix

static constexpr int STG_BYTES = 128 * KSTR * 2;
static constexpr int SMB_BIAS  = 8 * STG_BYTES;
static constexpr int SMB_TOT   = SMB_BIAS + 128 * 4;
__device__ __forceinline__ uint32_t stg_off(int arr, int st) {
    return (uint32_t)((arr * 2 + st) * STG_BYTES);
}

__global__ __launch_bounds__(256, 1) void gemm_bf16mma(const float* __restrict__ b1g,
                                                       const float* __restrict__ b2g,
                                                       int layer)
{
    extern __shared__ char smem[];
    const uint32_t sb = smem_u32(smem);
    const int tid = threadIdx.x;
    const int lane = tid & 31;
    const int w = tid >> 5;
    const int wm = (w & 3) * 32;
    const int wn = (w >> 2) * 64;
    const int m0 = blockIdx.y * 128;
    const int n0 = blockIdx.x * 128;

    if (tid < 128) {
        ((float*)(smem + SMB_BIAS))[tid] =
            b1g[layer * G4 + n0 + tid] + b2g[layer * G4 + n0 + tid];
    }

    const uint4* Ah = (const uint4*)g_ah;
    const uint4* Al = (const uint4*)g_al;
    const uint4* Bh = (const uint4*)(g_bh + (size_t)layer * G4 * Hh);
    const uint4* Bl = (const uint4*)(g_bl + (size_t)layer * G4 * Hh);

    float acc[2][8][4];
#pragma unroll
    for (int i = 0; i < 2; i++)
#pragma unroll
        for (int j = 0; j < 8; j++)
#pragma unroll
            for (int k = 0; k < 4; k++) acc[i][j][k] = 0.0f;

    const int a_row = (lane & 15);
    const int a_kof = (lane >> 4) << 3;
    const int b_row = (lane & 7) + ((lane >> 4) << 3);
    const int b_kof = ((lane >> 3) & 1) << 3;

    auto load_stage = [&](int kc, int st) {
#pragma unroll
        for (int r = 0; r < 4; r++) {
            int i = tid + r * 256;
            int row = i >> 3, c8 = i & 7;
            uint32_t d = (uint32_t)(row * (KSTR * 2) + c8 * 16);
            int gaix = (m0 + row) * 32 + kc * 8 + c8;
            int gbix = (n0 + row) * 32 + kc * 8 + c8;
            cpa16(sb + stg_off(0, st) + d, &Ah[gaix]);
            cpa16(sb + stg_off(1, st) + d, &Al[gaix]);
            cpa16(sb + stg_off(2, st) + d, &Bh[gbix]);
            cpa16(sb + stg_off(3, st) + d, &Bl[gbix]);
        }
        CPA_COMMIT();
    };

    load_stage(0, 0);

    for (int kc = 0; kc < 4; kc++) {
        const int st = kc & 1;
        if (kc < 3) { load_stage(kc + 1, st ^ 1); CPA_WAIT(1); }
        else        { CPA_WAIT(0); }
        __syncthreads();

        const uint32_t bAH = sb + stg_off(0, st);
        const uint32_t bAL = sb + stg_off(1, st);
        const uint32_t bBH = sb + stg_off(2, st);
        const uint32_t bBL = sb + stg_off(3, st);

#pragma unroll
        for (int ks = 0; ks < 4; ks++) {
            const int kh = ks * 16;
            uint32_t ah[2][4], al[2][4];
#pragma unroll
            for (int mt = 0; mt < 2; mt++) {
                uint32_t off = (uint32_t)(((wm + mt * 16 + a_row) * KSTR + kh + a_kof) * 2);
                ldsm4(ah[mt][0], ah[mt][1], ah[mt][2], ah[mt][3], bAH + off);
                ldsm4(al[mt][0], al[mt][1], al[mt][2], al[mt][3], bAL + off);
            }
            uint32_t bh[4][4], bl[4][4];
#pragma unroll
            for (int p = 0; p < 4; p++) {
                uint32_t off = (uint32_t)(((wn + p * 16 + b_row) * KSTR + kh + b_kof) * 2);
                ldsm4(bh[p][0], bh[p][1], bh[p][2], bh[p][3], bBH + off);
                ldsm4(bl[p][0], bl[p][1], bl[p][2], bl[p][3], bBL + off);
            }
#pragma unroll
            for (int mt = 0; mt < 2; mt++) {
#pragma unroll
                for (int p = 0; p < 4; p++) {
                    mma16816(acc[mt][2 * p + 0], ah[mt][0], ah[mt][1], ah[mt][2], ah[mt][3],
                             bh[p][0], bh[p][1]);
                    mma16816(acc[mt][2 * p + 0], ah[mt][0], ah[mt][1], ah[mt][2], ah[mt][3],
                             bl[p][0], bl[p][1]);
                    mma16816(acc[mt][2 * p + 0], al[mt][0], al[mt][1], al[mt][2], al[mt][3],
                             bh[p][0], bh[p][1]);
                    mma16816(acc[mt][2 * p + 1], ah[mt][0], ah[mt][1], ah[mt][2], ah[mt][3],
                             bh[p][2], bh[p][3]);
                    mma16816(acc[mt][2 * p + 1], ah[mt][0], ah[mt][1], ah[mt][2], ah[mt][3],
                             bl[p][2], bl[p][3]);
                    mma16816(acc[mt][2 * p + 1], al[mt][0], al[mt][1], al[mt][2], al[mt][3],
                             bh[p][2], bh[p][3]);
                }
            }
        }
        __syncthreads();
    }

    const float* bias = (const float*)(smem + SMB_BIAS);
    const int gid = lane >> 2;
    const int tig = lane & 3;
#pragma unroll
    for (int mt = 0; mt < 2; mt++) {
#pragma unroll
        for (int nt = 0; nt < 8; nt++) {
            int col = wn + nt * 8 + tig * 2;
            float b0 = bias[col], b1 = bias[col + 1];
            int gm0 = m0 + wm + mt * 16 + gid;
            float* p0 = &g_xp[(size_t)gm0 * G4 + n0 + col];
            float* p1 = &g_xp[(size_t)(gm0 + 8) * G4 + n0 + col];
            float2 v0 = { acc[mt][nt][0] + b0, acc[mt][nt][1] + b1 };
            float2 v1 = { acc[mt][nt][2] + b0, acc[mt][nt][3] + b1 };
            *(float2*)p0 = v0;
            *(float2*)p1 = v1;
        }
    }
}

// ---------------- clustered LSTM recurrence (exact R11 core) ----------------
// Per-source mbarriers (st.async tx counting), redp double-buffered by t&1,
// single __syncthreads per step. Layer 0 writes y directly as bf16 hi/lo into
// g_ah/g_al (the layer-1 GEMM's A operands) — eliminating the f32 y0
// intermediate and the layer-1 X conv_split. Layer 1 writes the f32 output.
__global__ __launch_bounds__(512, 1) __cluster_dims__(CL, 1, 1)
void lstm_rec(const float* __restrict__ Whh,
              float* __restrict__ yout,
              float* __restrict__ hT,
              float* __restrict__ cT,
              int layer)
{
    __shared__ __align__(16) float h_s[2][Hh];        // +1024 B between buffers
    __shared__ float redp[2][2][4][64];               // [t&1][half][gate][nl]
    __shared__ __align__(8) unsigned long long mbars[2][CL];

    const int tid = threadIdx.x;
    uint32_t rank;
    asm("mov.u32 %0, %%cluster_ctarank;" : "=r"(rank));
    const int b  = blockIdx.x / CL;
    const int n0 = (int)rank * 64;

    const int half = tid >> 8;            // 0/1: which K half
    const int sub  = tid & 255;
    const int gate = sub >> 6;
    const int nl   = sub & 63;
    const int G    = gate * 256 + n0 + nl;

    const float4* Wrow = (const float4*)(Whh + (size_t)layer * G4 * Hh
                                         + (size_t)G * Hh + half * 128);
    unsigned wreg[64];
#pragma unroll
    for (int q = 0; q < 32; q++) {
        float4 v = __ldg(&Wrow[q]);
        wreg[2 * q + 0] = pack_bf16x2(v.x, v.y);
        wreg[2 * q + 1] = pack_bf16x2(v.z, v.w);
    }

    const uint32_t lh0 = smem_u32(&h_s[0][0]);
    const uint32_t lm0 = smem_u32(&mbars[0][0]);

    for (int i = tid; i < Hh; i += 512) h_s[0][i] = 0.0f;
    if (tid == 0) {
#pragma unroll
        for (int i = 0; i < 2 * CL; i++) mbar_init(lm0 + i * 8u, 1);
#pragma unroll
        for (int p = 0; p < CL; p++) mbar_arrive_local(lm0 + p * 8u);  // buffer 0 phase 0 done
    }
    __syncthreads();
    CLUSTER_ARRIVE();
    CLUSTER_WAIT();

    const float* xp = g_xp + (size_t)b * Ss * G4 + G;

    float c_reg = 0.0f;

    // hoisted remote bases for cell threads (buffer offsets added per step)
    const int n_cell = n0 + (tid & 63);
    uint32_t rhB[CL], rmB[CL];
#pragma unroll
    for (int p = 0; p < CL; p++) {
        rhB[p] = mapa_u32(lh0 + (uint32_t)n_cell * 4u, p);
        rmB[p] = mapa_u32(lm0, p);
    }
    const uint32_t my_mofs = rank * 8u;   // mbars[.][my_rank]

    // this thread's two source chunks
    const int srcA = half * 2;
    const int srcB = half * 2 + 1;

    // output pointers
    __nv_bfloat16* yh = g_ah + (size_t)b * Ss * Hh;   // layer 0 dest (hi)
    __nv_bfloat16* yl = g_al + (size_t)b * Ss * Hh;   // layer 0 dest (lo)
    float* yf = yout + (size_t)b * Ss * Hh;           // layer 1 dest

    float xpv = (half == 0) ? __ldg(&xp[0]) : 0.0f;

    for (int t = 0; t < Ss; t++) {
        const uint32_t cb = (uint32_t)(t & 1);
        const uint32_t nb = cb ^ 1u;
        const uint32_t par = (uint32_t)((t >> 1) & 1);

        // arm next buffer's 4 source-mbars early (spread across 4 threads)
        if (tid < CL) mbar_arm_tx(lm0 + (nb * CL + (uint32_t)tid) * 8u, 256u);

        float xpn = (half == 0)
                  ? __ldg(&xp[(size_t)(t + 1 < Ss ? t + 1 : t) * G4]) : 0.0f;

        // ---- half-dot, chunked by source CTA; wait right before consuming ----
        const ulonglong2* hv = (const ulonglong2*)&h_s[cb][half * 128];
        ull acc0 = 0ull, acc1 = 0ull;

        mbar_wait_cluster(lm0 + (cb * CL + srcA) * 8u, par);
#pragma unroll
        for (int q = 0; q < 16; q++) {
            ulonglong2 hh = hv[q];
            fma2(acc0, hh.x, expand_a(wreg[2 * q + 0]));
            fma2(acc1, hh.y, expand_b(wreg[2 * q + 1]));
        }
        mbar_wait_cluster(lm0 + (cb * CL + srcB) * 8u, par);
#pragma unroll
        for (int q = 16; q < 32; q++) {
            ulonglong2 hh = hv[q];
            fma2(acc0, hh.x, expand_a(wreg[2 * q + 0]));
            fma2(acc1, hh.y, expand_b(wreg[2 * q + 1]));
        }

        float s0, s1, s2, s3;
        unpack2(acc0, s0, s1);
        unpack2(acc1, s2, s3);
        redp[cb][half][gate][nl] = ((s0 + s2) + (s1 + s3)) + xpv;
        __syncthreads();

        if (tid < 64) {
            float iv = redp[cb][0][0][tid] + redp[cb][1][0][tid];
            float fv = redp[cb][0][1][tid] + redp[cb][1][1][tid];
            float gv = redp[cb][0][2][tid] + redp[cb][1][2][tid];
            float ov = redp[cb][0][3][tid] + redp[cb][1][3][tid];
            float c  = sig_f(fv) * c_reg + sig_f(iv) * tanh_f(gv);
            float h  = sig_f(ov) * tanh_f(c);
            c_reg = c;
            const uint32_t hofs = nb * (uint32_t)(Hh * 4);
            const uint32_t mofs = nb * (uint32_t)(CL * 8) + my_mofs;
#pragma unroll
            for (int p = 0; p < CL; p++)
                st_async_f32(rhB[p] + hofs, rmB[p] + mofs, h);
            if (layer == 0) {
                // write bf16 hi/lo split directly (identical math to conv_split)
                __nv_bfloat16 hh_ = __float2bfloat16(h);
                __nv_bfloat16 hl_ = __float2bfloat16(h - __bfloat162float(hh_));
                size_t idx = (size_t)t * Hh + n_cell;
                yh[idx] = hh_;
                yl[idx] = hl_;
            } else {
                yf[(size_t)t * Hh + n_cell] = h;
            }
            if (t == Ss - 1) { hT[b * Hh + n_cell] = h; cT[b * Hh + n_cell] = c; }
        }
        xpv = xpn;
        // no second barrier: redp double-buffering makes next step's writes safe
    }

    // no CTA may exit while peers' st.async into its SMEM could be in flight
    CLUSTER_ARRIVE();
    CLUSTER_WAIT();
}

// ---------------- launch ----------------
extern "C" void kernel_launch(void* const* d_in, const int* in_sizes, int n_in,
                              void* d_out, int out_size)
{
    (void)in_sizes; (void)n_in; (void)out_size;
    const float* x    = (const float*)d_in[0];   // [B,S,H]
    const float* Wih  = (const float*)d_in[1];   // [L,4H,H]
    const float* bih  = (const float*)d_in[2];   // [L,4H]
    const float* Whh  = (const float*)d_in[3];   // [L,4H,H]
    const float* bhh  = (const float*)d_in[4];   // [L,4H]

    float* out = (float*)d_out;
    float* y_x = out;
    float* hT  = out + (size_t)Bb * Ss * Hh;
    float* cT  = hT + (size_t)Ll * Bb * Hh;

    cudaFuncSetAttribute(gemm_bf16mma, cudaFuncAttributeMaxDynamicSharedMemorySize, SMB_TOT);

    __nv_bfloat16 *ah, *al, *bh, *bl;
    cudaGetSymbolAddress((void**)&ah, g_ah);
    cudaGetSymbolAddress((void**)&al, g_al);
    cudaGetSymbolAddress((void**)&bh, g_bh);
    cudaGetSymbolAddress((void**)&bl, g_bl);

    const int nX4 = (Bb * Ss * Hh) / 4;
    const int nW4 = (G4 * Hh) / 4;

    dim3 ggrid(G4 / 128, (Bb * Ss) / 128);

    // upfront conversions: X (layer 0) + both W layers
    conv_split<<<nX4 / 256, 256>>>(x, ah, al, nX4);
    conv_split<<<nW4 / 256, 256>>>(Wih, bh, bl, nW4);
    conv_split<<<nW4 / 256, 256>>>(Wih + (size_t)G4 * Hh,
                                   bh + (size_t)G4 * Hh,
                                   bl + (size_t)G4 * Hh, nW4);

    for (int layer = 0; layer < Ll; layer++) {
        gemm_bf16mma<<<ggrid, 256, SMB_TOT>>>(bih, bhh, layer);
        // layer 0 rec overwrites g_ah/g_al with y0's bf16 hi/lo (gemm L0 already
        // consumed them); layer 1 rec writes the f32 output.
        lstm_rec<<<NCTA, 512>>>(Whh, y_x,
                                hT + (size_t)layer * Bb * Hh,
                                cT + (size_t)layer * Bb * Hh,
                                layer);
    }
}